// round 10
// baseline (speedup 1.0000x reference)
#include <cuda_runtime.h>

typedef unsigned long long u64t;

__device__ __forceinline__ u64t fma2(u64t a, u64t b, u64t c) {
    u64t d;
    asm("fma.rn.f32x2 %0, %1, %2, %3;" : "=l"(d) : "l"(a), "l"(b), "l"(c));
    return d;
}
__device__ __forceinline__ u64t add2(u64t a, u64t b) {
    u64t d;
    asm("add.rn.f32x2 %0, %1, %2;" : "=l"(d) : "l"(a), "l"(b));
    return d;
}
__device__ __forceinline__ u64t pk2(float lo, float hi) {
    u64t d;
    asm("mov.b64 %0, {%1, %2};" : "=l"(d) : "f"(lo), "f"(hi));
    return d;
}
__device__ __forceinline__ void unpk(u64t v, float& lo, float& hi) {
    asm("mov.b64 {%0, %1}, %2;" : "=f"(lo), "=f"(hi) : "l"(v));
}
__device__ __forceinline__ float fsqrt_ap(float x) {
    float y;
    asm("sqrt.approx.f32 %0, %1;" : "=f"(y) : "f"(x));
    return y;
}
__device__ __forceinline__ u64t shx1(u64t v) {
    unsigned lo = (unsigned)v, hi = (unsigned)(v >> 32);
    lo = __shfl_xor_sync(0xffffffffu, lo, 1);
    hi = __shfl_xor_sync(0xffffffffu, hi, 1);
    return ((u64t)hi << 32) | lo;
}

// ---- weight region (u64t units) ----
// x-order (new k): [rot 0..8, jtr 9..11, feat 12..17, bone 18, pad 19]
//   old-k map K(m): m<12 -> m ; 12..17 -> m+1 ; 18 -> 12 ; 19 -> (zero)
// sW1': [24 j][10 kp][20 r]  u64 = (W1[j][r][K(2kp)], W1[j][r][K(2kp+1)])
// sW2 : [24 j][20 k][3 dp]   (k=19 row = b2; fed by hs[9]==1 on odd lane)
// sW0': [144 kp][6 d]        u64 = (W0[d][F(2kp)], W0[d][F(2kp+1)])  (F = f'->f)
// sB1': [24 j][20 r]         u64 = (b1, 0)
// sB0': [6 d]                u64 = (b0, 0)
#define OW1 0
#define OW2 4800
#define OW0 6240
#define OB1 7104
#define OB0 7584
#define SM_U64 7590            // 60720 B

// ---- stash: element-major, 292 floats/element ----
// f' = 12*J + i : i in [0,9) = rot i ; i in [9,12) = jtr c  (adjacent pairs!)
#define ESTRIDE 292
#define STASH_WORDS (128 * ESTRIDE)
#define SMEM_BYTES  (SM_U64 * 8 + STASH_WORDS * 4)    // 210224 B

template<int J, int PS, int WS>
__device__ __forceinline__ void do_joint(
    float* __restrict__ se, int half, const u64t* __restrict__ sm,
    u64t (&fslot)[4][3], float (&jx)[4], float (&jy)[4], float (&jz)[4],
    const u64t (&g)[3])
{
    // x pairs: 6 from one aligned 48B block, 3 from fslot/g, 1 packed bone
    u64t xp[10];
    {
        const ulonglong2* xq = (const ulonglong2*)(se + 12*J);
        ulonglong2 q0 = xq[0], q1 = xq[1], q2 = xq[2];
        xp[0] = q0.x; xp[1] = q0.y; xp[2] = q1.x;
        xp[3] = q1.y; xp[4] = q2.x; xp[5] = q2.y;
    }
    float rr8, jxv, jyv, jzv;
    unpk(xp[4], rr8, jxv);          // (rot8, jtr0)
    unpk(xp[5], jyv, jzv);          // (jtr1, jtr2)
    (void)rr8;

    float dx, dy, dz;
    if (PS < 0) { dx = jxv; dy = jyv; dz = jzv; }
    else {
        const int P = (PS < 0) ? 0 : PS;
        dx = jxv - jx[P]; dy = jyv - jy[P]; dz = jzv - jz[P];
    }
    float bone = fsqrt_ap(dx*dx + dy*dy + dz*dz);
    jx[WS] = jxv; jy[WS] = jyv; jz[WS] = jzv;

    if (PS < 0) { xp[6] = g[0]; xp[7] = g[1]; xp[8] = g[2]; }
    else {
        const int P = (PS < 0) ? 0 : PS;
        xp[6] = fslot[P][0]; xp[7] = fslot[P][1]; xp[8] = fslot[P][2];
    }
    xp[9] = pk2(bone, bone);        // weight hi is 0 -> hi lane contributes 0

    // ---- layer 1: 10 rows (this half), acc = (even-kp partial, odd-kp partial) ----
    u64t acc[10];
    {
        const ulonglong2* bb = (const ulonglong2*)(sm + OB1 + J*20 + 10*half);
        ulonglong2 b0q = bb[0], b1q = bb[1], b2q = bb[2], b3q = bb[3], b4q = bb[4];
        acc[0]=b0q.x; acc[1]=b0q.y; acc[2]=b1q.x; acc[3]=b1q.y; acc[4]=b2q.x;
        acc[5]=b2q.y; acc[6]=b3q.x; acc[7]=b3q.y; acc[8]=b4q.x; acc[9]=b4q.y;
    }
#pragma unroll
    for (int i = 0; i < 10; ++i) {
        const ulonglong2* wr = (const ulonglong2*)(sm + OW1 + (J*10 + i)*20 + 10*half);
        ulonglong2 wa = wr[0], wb = wr[1], wc = wr[2], wd = wr[3], we = wr[4];
        u64t xx = xp[i];
        acc[0] = fma2(xx, wa.x, acc[0]);
        acc[1] = fma2(xx, wa.y, acc[1]);
        acc[2] = fma2(xx, wb.x, acc[2]);
        acc[3] = fma2(xx, wb.y, acc[3]);
        acc[4] = fma2(xx, wc.x, acc[4]);
        acc[5] = fma2(xx, wc.y, acc[5]);
        acc[6] = fma2(xx, wd.x, acc[6]);
        acc[7] = fma2(xx, wd.y, acc[7]);
        acc[8] = fma2(xx, we.x, acc[8]);
        acc[9] = fma2(xx, we.y, acc[9]);
    }

    // combine halves + relu
    float hs[10];
#pragma unroll
    for (int r = 0; r < 10; ++r) {
        float a, b; unpk(acc[r], a, b);
        hs[r] = fmaxf(a + b, 0.f);
    }
    if (half) hs[9] = 1.0f;   // global row 19 pad -> feeds b2 row (k=19) of sW2

    // ---- layer 2: preload 30 contiguous u64 weights, FMA burst (R9 scheme) ----
    ulonglong2 wz[15];
    {
        const ulonglong2* wp = (const ulonglong2*)(sm + OW2 + (J*20 + 10*half)*3);
#pragma unroll
        for (int i = 0; i < 15; ++i) wz[i] = wp[i];
    }
    u64t o0 = 0ull, o1 = 0ull, o2 = 0ull;
#pragma unroll
    for (int i = 0; i < 5; ++i) {
        u64t x0 = pk2(hs[2*i],   hs[2*i]);
        u64t x1 = pk2(hs[2*i+1], hs[2*i+1]);
        o0 = fma2(x0, wz[3*i  ].x, o0);
        o1 = fma2(x0, wz[3*i  ].y, o1);
        o2 = fma2(x0, wz[3*i+1].x, o2);
        o0 = fma2(x1, wz[3*i+1].y, o0);
        o1 = fma2(x1, wz[3*i+2].x, o1);
        o2 = fma2(x1, wz[3*i+2].y, o2);
    }
    o0 = add2(o0, shx1(o0));
    o1 = add2(o1, shx1(o1));
    o2 = add2(o2, shx1(o2));

    fslot[WS][0] = o0; fslot[WS][1] = o1; fslot[WS][2] = o2;

    float v0, v1, v2, v3, v4, v5;
    unpk(o0, v0, v1); unpk(o1, v2, v3); unpk(o2, v4, v5);
    float w0s = half ? v3 : v0;
    float w1s = half ? v4 : v1;
    float w2s = half ? v5 : v2;
    float* dst = se + 12*J + 3*half;
    dst[0] = w0s; dst[1] = w1s; dst[2] = w2s;
}

__global__ void __launch_bounds__(256, 1)
pose_kernel(const float* __restrict__ rots, const float* __restrict__ jtrs,
            const float* __restrict__ W0, const float* __restrict__ b0,
            const float* __restrict__ W1, const float* __restrict__ b1,
            const float* __restrict__ W2, const float* __restrict__ b2,
            float* __restrict__ out)
{
    extern __shared__ u64t sm[];
    float* stash = (float*)(sm + SM_U64);
    const int tid = threadIdx.x;

    // ---- staging: coalesced LDG.128 -> contiguous STS (f' interleaved layout) ----
    {
        const float4* gr4 = (const float4*)(rots + (size_t)blockIdx.x * 128 * 216);
        const float4* gt4 = (const float4*)(jtrs + (size_t)blockIdx.x * 128 * 72);
#pragma unroll 3
        for (int i = 0; i < 27; ++i) {                  // rots: 6912 float4
            int G = i*256 + tid;
            float4 v = gr4[G];
            int e = G / 54, f4 = G % 54;
            float* dst = stash + e*ESTRIDE;
            int fo = 4*f4;
            float vv[4] = {v.x, v.y, v.z, v.w};
#pragma unroll
            for (int c = 0; c < 4; ++c) {
                int f = fo + c;
                int Jc = f / 9;                         // f' = f + 3*Jc
                dst[f + 3*Jc] = vv[c];
            }
        }
#pragma unroll 3
        for (int i = 0; i < 9; ++i) {                   // jtrs: 2304 float4
            int G = i*256 + tid;
            float4 v = gt4[G];
            int e = G / 18, f4 = G % 18;
            float* dst = stash + e*ESTRIDE;
            int mo = 4*f4;
            float vv[4] = {v.x, v.y, v.z, v.w};
#pragma unroll
            for (int c = 0; c < 4; ++c) {
                int m = mo + c;
                int Jt = m / 3;                         // f' = m + 9*Jt + 9
                dst[m + 9*Jt + 9] = vv[c];
            }
        }
    }

    // ---- weight packing ----
    for (int idx = tid; idx < 24*10*20; idx += 256) {   // sW1' [j][kp][20 r]
        int r = idx % 20; int t = idx / 20; int i = t % 10; int j = t / 10;
        int m0 = 2*i, m1 = 2*i + 1;
        float lo = 0.f, hi = 0.f;
        if (r < 19) {
            int k0 = (m0 < 12) ? m0 : (m0 < 18 ? m0 + 1 : 12);
            lo = W1[(j*19 + r)*19 + k0];
            if (m1 < 19) {
                int k1 = (m1 < 12) ? m1 : (m1 < 18 ? m1 + 1 : 12);
                hi = W1[(j*19 + r)*19 + k1];
            }
        }
        sm[OW1 + idx] = pk2(lo, hi);
    }
    for (int idx = tid; idx < 24*20*3; idx += 256) {    // sW2 [j][20 k][3 dp]
        int dp = idx % 3; int t = idx / 3; int k = t % 20; int j = t / 20;
        float lo, hi;
        if (k < 19) { lo = W2[(j*6 + 2*dp)*19 + k]; hi = W2[(j*6 + 2*dp + 1)*19 + k]; }
        else        { lo = b2[j*6 + 2*dp];          hi = b2[j*6 + 2*dp + 1]; }
        sm[OW2 + idx] = pk2(lo, hi);
    }
    for (int idx = tid; idx < 144*6; idx += 256) {      // sW0' [144 kp][6 d]
        int d = idx % 6; int kp = idx / 6;
        int m0 = 2*kp, m1 = 2*kp + 1;
        int J0 = m0/12, i0 = m0%12;
        int f0 = (i0 < 9) ? (9*J0 + i0) : (216 + 3*J0 + (i0 - 9));
        int J1 = m1/12, i1 = m1%12;
        int f1 = (i1 < 9) ? (9*J1 + i1) : (216 + 3*J1 + (i1 - 9));
        sm[OW0 + idx] = pk2(W0[d*288 + f0], W0[d*288 + f1]);
    }
    for (int idx = tid; idx < 24*20; idx += 256) {      // sB1' [j][20 r]
        int r = idx % 20; int j = idx / 20;
        float lo = (r < 19) ? b1[j*19 + r] : 0.f;
        sm[OB1 + idx] = pk2(lo, 0.f);
    }
    if (tid < 6) sm[OB0 + tid] = pk2(b0[tid], 0.f);
    __syncthreads();

    const int e    = tid >> 1;
    const int half = tid & 1;
    float* se = stash + e*ESTRIDE;

    // ---- pass 1: gfeat, x pairs direct from stash (no pk2) ----
    u64t acc6[6];
    if (half == 0) {
#pragma unroll
        for (int d = 0; d < 6; ++d) acc6[d] = sm[OB0 + d];
    } else {
#pragma unroll
        for (int d = 0; d < 6; ++d) acc6[d] = 0ull;
    }
    {
        const ulonglong2* xq = (const ulonglong2*)(se + 144*half);
        const u64t* wbase = sm + OW0 + (72*half)*6;
#pragma unroll 4
        for (int q = 0; q < 36; ++q) {
            ulonglong2 xv = xq[q];                      // kp 2q, 2q+1
            const ulonglong2* wp = (const ulonglong2*)(wbase + q*12);
            ulonglong2 w0 = wp[0], w1 = wp[1], w2 = wp[2];
            ulonglong2 w3 = wp[3], w4 = wp[4], w5 = wp[5];
            acc6[0] = fma2(xv.x, w0.x, acc6[0]);
            acc6[1] = fma2(xv.x, w0.y, acc6[1]);
            acc6[2] = fma2(xv.x, w1.x, acc6[2]);
            acc6[3] = fma2(xv.x, w1.y, acc6[3]);
            acc6[4] = fma2(xv.x, w2.x, acc6[4]);
            acc6[5] = fma2(xv.x, w2.y, acc6[5]);
            acc6[0] = fma2(xv.y, w3.x, acc6[0]);
            acc6[1] = fma2(xv.y, w3.y, acc6[1]);
            acc6[2] = fma2(xv.y, w4.x, acc6[2]);
            acc6[3] = fma2(xv.y, w4.y, acc6[3]);
            acc6[4] = fma2(xv.y, w5.x, acc6[4]);
            acc6[5] = fma2(xv.y, w5.y, acc6[5]);
        }
    }
    u64t g[3];
#pragma unroll
    for (int dp = 0; dp < 3; ++dp) {
        float a0, a1, c0, c1;
        unpk(acc6[2*dp],     a0, a1);
        unpk(acc6[2*dp + 1], c0, c1);
        u64t pr = pk2(a0 + a1, c0 + c1);
        g[dp] = add2(pr, shx1(pr));
    }

    // ---- pass 2: joint chain ----
    u64t fslot[4][3];
    float jx[4], jy[4], jz[4];

    do_joint< 0,-1,0>(se, half, sm, fslot, jx, jy, jz, g);
    do_joint< 1, 0,1>(se, half, sm, fslot, jx, jy, jz, g);
    do_joint< 2, 0,2>(se, half, sm, fslot, jx, jy, jz, g);
    do_joint< 3, 0,3>(se, half, sm, fslot, jx, jy, jz, g);
    do_joint< 4, 1,0>(se, half, sm, fslot, jx, jy, jz, g);
    do_joint< 5, 2,1>(se, half, sm, fslot, jx, jy, jz, g);
    do_joint< 6, 3,2>(se, half, sm, fslot, jx, jy, jz, g);
    do_joint< 7, 0,3>(se, half, sm, fslot, jx, jy, jz, g);
    do_joint< 8, 1,0>(se, half, sm, fslot, jx, jy, jz, g);
    do_joint< 9, 2,1>(se, half, sm, fslot, jx, jy, jz, g);
    do_joint<10, 3,2>(se, half, sm, fslot, jx, jy, jz, g);
    do_joint<11, 0,2>(se, half, sm, fslot, jx, jy, jz, g);
    do_joint<12, 1,2>(se, half, sm, fslot, jx, jy, jz, g);
    do_joint<13, 1,0>(se, half, sm, fslot, jx, jy, jz, g);
    do_joint<14, 1,3>(se, half, sm, fslot, jx, jy, jz, g);
    do_joint<15, 2,1>(se, half, sm, fslot, jx, jy, jz, g);
    do_joint<16, 0,1>(se, half, sm, fslot, jx, jy, jz, g);
    do_joint<17, 3,0>(se, half, sm, fslot, jx, jy, jz, g);
    do_joint<18, 1,3>(se, half, sm, fslot, jx, jy, jz, g);
    do_joint<19, 0,1>(se, half, sm, fslot, jx, jy, jz, g);
    do_joint<20, 3,0>(se, half, sm, fslot, jx, jy, jz, g);
    do_joint<21, 1,3>(se, half, sm, fslot, jx, jy, jz, g);
    do_joint<22, 0,1>(se, half, sm, fslot, jx, jy, jz, g);
    do_joint<23, 3,0>(se, half, sm, fslot, jx, jy, jz, g);

    // ---- epilogue: coalesced store of all 128 x 144 outputs ----
    __syncthreads();
    float* og = out + (size_t)blockIdx.x * (128 * 144);
#pragma unroll 8
    for (int i = 0; i < 72; ++i) {
        int G = i*256 + tid;
        int ee = G / 144, p = G % 144;
        int J = p / 6;                                  // f' = p + 6J
        og[G] = stash[ee*ESTRIDE + p + 6*J];
    }
}

extern "C" void kernel_launch(void* const* d_in, const int* in_sizes, int n_in,
                              void* d_out, int out_size) {
    (void)n_in; (void)out_size;
    const float* rots = (const float*)d_in[0];
    const float* jtrs = (const float*)d_in[1];
    const float* W0   = (const float*)d_in[2];
    const float* b0   = (const float*)d_in[3];
    const float* W1   = (const float*)d_in[4];
    const float* b1   = (const float*)d_in[5];
    const float* W2   = (const float*)d_in[6];
    const float* b2   = (const float*)d_in[7];
    float* out = (float*)d_out;

    int n = in_sizes[0] / 216;        // B (131072 -> divisible by 128)
    int grid = n / 128;

    cudaFuncSetAttribute(pose_kernel, cudaFuncAttributeMaxDynamicSharedMemorySize, SMEM_BYTES);
    pose_kernel<<<grid, 256, SMEM_BYTES>>>(rots, jtrs, W0, b0, W1, b1, W2, b2, out);
}